// round 14
// baseline (speedup 1.0000x reference)
#include <cuda_runtime.h>
#include <cuda_bf16.h>

#define EPS 1e-6f
#define ITERS 20

typedef unsigned long long u64;

__device__ __forceinline__ float frcp(float x) {
    float y;
    asm("rcp.approx.ftz.f32 %0, %1;" : "=f"(y) : "f"(x));
    return y;
}
__device__ __forceinline__ u64 pack2(float lo, float hi) {
    u64 r;
    asm("mov.b64 %0, {%1, %2};" : "=l"(r) : "f"(lo), "f"(hi));
    return r;
}
__device__ __forceinline__ void unpack2(u64 v, float& lo, float& hi) {
    asm("mov.b64 {%0, %1}, %2;" : "=f"(lo), "=f"(hi) : "l"(v));
}
__device__ __forceinline__ u64 mul2(u64 a, u64 b) {
    u64 d;
    asm("mul.rn.f32x2 %0, %1, %2;" : "=l"(d) : "l"(a), "l"(b));
    return d;
}
__device__ __forceinline__ u64 add2(u64 a, u64 b) {
    u64 d;
    asm("add.rn.f32x2 %0, %1, %2;" : "=l"(d) : "l"(a), "l"(b));
    return d;
}
__device__ __forceinline__ u64 fma2(u64 a, u64 b, u64 c) {
    u64 d;
    asm("fma.rn.f32x2 %0, %1, %2, %3;" : "=l"(d) : "l"(a), "l"(b), "l"(c));
    return d;
}

// Per-lane reciprocal on a packed pair: 2 MUFU ops, pack/unpack alias to reg halves.
// Moves normalization work off the saturated FMA pipe onto the idle MUFU pipe.
__device__ __forceinline__ u64 rcp2(u64 x) {
    float lo, hi;
    unpack2(x, lo, hi);
    return pack2(frcp(lo), frcp(hi));
}

// Phase 1 helper: pre/post for one token from its first two float4s.
__device__ __forceinline__ void prepost(float4 v0, float4 v1, int t, bool st,
                                        float4* op, float4* oq,
                                        float s0, float s1, const float* sb)
{
    float p[4] = {v0.x, v0.y, v0.z, v0.w};
    #pragma unroll
    for (int i = 0; i < 4; i++)
        p[i] = frcp(1.0f + __expf(-fmaf(p[i], s0, sb[i]))) + EPS;
    if (st) __stcs(op + t, make_float4(p[0], p[1], p[2], p[3]));

    float q[4] = {v1.x, v1.y, v1.z, v1.w};
    #pragma unroll
    for (int i = 0; i < 4; i++)
        q[i] = 2.0f * frcp(1.0f + __expf(-fmaf(q[i], s1, sb[4 + i])));
    if (st) __stcs(oq + t, make_float4(q[0], q[1], q[2], q[3]));
}

// Phase 2/3 helper: comb matrix (softmax rows + EPS) for one token.
__device__ __forceinline__ void combmat(const float* __restrict__ mixes, int t,
                                        float s2, const float* sb, float m[16])
{
    const float4* mp = (const float4*)(mixes + (size_t)t * 24);
    float4 v2 = __ldcs(mp + 2);
    float4 v3 = __ldcs(mp + 3);
    float4 v4 = __ldcs(mp + 4);
    float4 v5 = __ldcs(mp + 5);
    float mm[16] = {v2.x, v2.y, v2.z, v2.w,
                    v3.x, v3.y, v3.z, v3.w,
                    v4.x, v4.y, v4.z, v4.w,
                    v5.x, v5.y, v5.z, v5.w};
    #pragma unroll
    for (int i = 0; i < 4; i++) {
        #pragma unroll
        for (int j = 0; j < 4; j++)
            mm[i * 4 + j] = __expf(fmaf(mm[i * 4 + j], s2, sb[8 + i * 4 + j]));
        float inv = frcp((mm[i * 4] + mm[i * 4 + 1]) + (mm[i * 4 + 2] + mm[i * 4 + 3]));
        #pragma unroll
        for (int j = 0; j < 4; j++)
            m[i * 4 + j] = fmaf(mm[i * 4 + j], inv, EPS);
    }
}

__global__ __launch_bounds__(256, 4)
void hc_sinkhorn_kernel(const float* __restrict__ mixes,
                        const float* __restrict__ hc_scale,
                        const float* __restrict__ hc_base,
                        float* __restrict__ out,
                        int n_tok, int n_half)
{
    __shared__ float sb[24];
    __shared__ float ss[3];
    if (threadIdx.x < 24) sb[threadIdx.x] = hc_base[threadIdx.x];
    if (threadIdx.x < 3)  ss[threadIdx.x] = hc_scale[threadIdx.x];
    __syncthreads();

    const int t = blockIdx.x * blockDim.x + threadIdx.x;
    if (t >= n_half) return;

    const int ta = t;
    const int tb = t + n_half;
    const bool vb = (tb < n_tok);
    const int tbe = vb ? tb : ta;

    const float s0 = ss[0], s1 = ss[1], s2 = ss[2];
    float4* op = (float4*)out;
    float4* oq = (float4*)(out + (size_t)n_tok * 4);

    // ---- Phase 1: pre/post for both tokens (low register footprint) ----
    {
        const float4* mpa = (const float4*)(mixes + (size_t)ta * 24);
        const float4* mpb = (const float4*)(mixes + (size_t)tbe * 24);
        float4 a0 = __ldcs(mpa + 0), a1 = __ldcs(mpa + 1);
        float4 b0 = __ldcs(mpb + 0), b1 = __ldcs(mpb + 1);
        prepost(a0, a1, ta, true, op, oq, s0, s1, sb);
        prepost(b0, b1, tbe, vb, op, oq, s0, s1, sb);
    }

    // ---- Phase 2+3: comb matrices, pack token-pairs into f32x2 lanes ----
    u64 M[16];
    {
        float ml[16];
        combmat(mixes, ta, s2, sb, ml);
        float mh[16];
        combmat(mixes, tbe, s2, sb, mh);
        #pragma unroll
        for (int k = 0; k < 16; k++)
            M[k] = pack2(ml[k], mh[k]);
    }

    // ---- Sinkhorn with exact per-pass reciprocals (MUFU), matvecs on FMA pipe ----
    u64 r0, r1, r2, r3, c0, c1, c2, c3;

    // Initial col normalize (r = 1): c_j = 1/colsum_j
    {
        u64 S0 = add2(add2(M[0], M[4]), add2(M[8],  M[12]));
        u64 S1 = add2(add2(M[1], M[5]), add2(M[9],  M[13]));
        u64 S2 = add2(add2(M[2], M[6]), add2(M[10], M[14]));
        u64 S3 = add2(add2(M[3], M[7]), add2(M[11], M[15]));
        c0 = rcp2(S0);
        c1 = rcp2(S1);
        c2 = rcp2(S2);
        c3 = rcp2(S3);
    }

    #pragma unroll 1
    for (int it = 0; it < ITERS - 1; it++) {
        // Row pass: T_i = sum_j M[i][j]*c_j ; r_i = 1/T_i
        u64 T0 = mul2(M[0],  c0);
        u64 T1 = mul2(M[4],  c0);
        u64 T2 = mul2(M[8],  c0);
        u64 T3 = mul2(M[12], c0);
        T0 = fma2(M[1],  c1, T0);
        T1 = fma2(M[5],  c1, T1);
        T2 = fma2(M[9],  c1, T2);
        T3 = fma2(M[13], c1, T3);
        T0 = fma2(M[2],  c2, T0);
        T1 = fma2(M[6],  c2, T1);
        T2 = fma2(M[10], c2, T2);
        T3 = fma2(M[14], c2, T3);
        T0 = fma2(M[3],  c3, T0);
        T1 = fma2(M[7],  c3, T1);
        T2 = fma2(M[11], c3, T2);
        T3 = fma2(M[15], c3, T3);
        r0 = rcp2(T0);
        r1 = rcp2(T1);
        r2 = rcp2(T2);
        r3 = rcp2(T3);

        // Col pass: S_j = sum_i M[i][j]*r_i ; c_j = 1/S_j
        u64 S0 = mul2(M[0], r0);
        u64 S1 = mul2(M[1], r0);
        u64 S2 = mul2(M[2], r0);
        u64 S3 = mul2(M[3], r0);
        S0 = fma2(M[4],  r1, S0);
        S1 = fma2(M[5],  r1, S1);
        S2 = fma2(M[6],  r1, S2);
        S3 = fma2(M[7],  r1, S3);
        S0 = fma2(M[8],  r2, S0);
        S1 = fma2(M[9],  r2, S1);
        S2 = fma2(M[10], r2, S2);
        S3 = fma2(M[11], r2, S3);
        S0 = fma2(M[12], r3, S0);
        S1 = fma2(M[13], r3, S1);
        S2 = fma2(M[14], r3, S2);
        S3 = fma2(M[15], r3, S3);
        c0 = rcp2(S0);
        c1 = rcp2(S1);
        c2 = rcp2(S2);
        c3 = rcp2(S3);
    }

    // ---- Epilogue: N_ij = M_ij * c_j * r_i (last col pass exact -> col sums = 1) ----
    float4* oc = (float4*)(out + (size_t)n_tok * 8);
    u64 rr[4] = {r0, r1, r2, r3};
    u64 cc[4] = {c0, c1, c2, c3};
    #pragma unroll
    for (int i = 0; i < 4; i++) {
        float a0, a1, a2, a3, b0, b1, b2, b3;
        u64 n0 = mul2(mul2(M[i * 4 + 0], cc[0]), rr[i]);
        u64 n1 = mul2(mul2(M[i * 4 + 1], cc[1]), rr[i]);
        u64 n2 = mul2(mul2(M[i * 4 + 2], cc[2]), rr[i]);
        u64 n3 = mul2(mul2(M[i * 4 + 3], cc[3]), rr[i]);
        unpack2(n0, a0, b0);
        unpack2(n1, a1, b1);
        unpack2(n2, a2, b2);
        unpack2(n3, a3, b3);
        __stcs(oc + (size_t)ta * 4 + i, make_float4(a0, a1, a2, a3));
        if (vb) __stcs(oc + (size_t)tb * 4 + i, make_float4(b0, b1, b2, b3));
    }
}

extern "C" void kernel_launch(void* const* d_in, const int* in_sizes, int n_in,
                              void* d_out, int out_size)
{
    const float* mixes    = (const float*)d_in[0];
    const float* hc_scale = (const float*)d_in[1];
    const float* hc_base  = (const float*)d_in[2];

    const int n_tok  = in_sizes[0] / 24;
    const int n_half = (n_tok + 1) / 2;
    const int block  = 256;
    const int grid   = (n_half + block - 1) / block;

    hc_sinkhorn_kernel<<<grid, block>>>(mixes, hc_scale, hc_base,
                                        (float*)d_out, n_tok, n_half);
}